// round 15
// baseline (speedup 1.0000x reference)
#include <cuda_runtime.h>
#include <cuda_fp16.h>

#define NN 100000
#define NE 1600000
#define NG 512
#define NB 98   // ceil(NN/1024)

// ---- scratch (device globals; no allocation allowed) ----
__device__ int    g_degout[NN];
__device__ int    g_degin[NN];
__device__ float  g_rout[NN];
__device__ float  g_rin[NN];
__device__ int    g_rowptr[NN + 1];
__device__ int    g_cur[NN];
__device__ int    g_partial[NB];
__device__ int    g_base[NB];
__device__ int    g_csrc[NE];
__device__ __half g_xs[NN * 128];     // fp16(x * rout), 25.6 MB
__device__ __half g_h2in[NN * 64];    // 12.8 MB
__device__ float  g_gsum[NG * 64];
__device__ int    g_gcnt[NG];

// ---------------------------------------------------------------------------
__global__ void zero_small_kernel() {
    int i = blockIdx.x * blockDim.x + threadIdx.x;
    int stride = gridDim.x * blockDim.x;
    for (int j = i; j < NN; j += stride) { g_degout[j] = 0; g_degin[j] = 0; }
    for (int j = i; j < NG * 64; j += stride) g_gsum[j] = 0.f;
    for (int j = i; j < NG; j += stride) g_gcnt[j] = 0;
}

__global__ void degree_kernel(const int* __restrict__ src, const int* __restrict__ dst) {
    int e = blockIdx.x * blockDim.x + threadIdx.x;
    if (e < NE) {
        atomicAdd(&g_degout[src[e]], 1);
        atomicAdd(&g_degin[dst[e]], 1);
    }
}

// xs[n][d] = fp16( x[n][d] * rsqrt(degout[n]) ); lane 0 also emits rout/rin
__global__ void xscale_kernel(const float* __restrict__ x) {
    int i = blockIdx.x * blockDim.x + threadIdx.x;   // float4 index
    int total = NN * 128 / 4;
    if (i >= total) return;
    int node = i >> 5;
    float r = rsqrtf((float)max(g_degout[node], 1));
    if ((i & 31) == 0) {
        g_rout[node] = r;
        g_rin[node]  = rsqrtf((float)max(g_degin[node], 1));
    }
    float4 v = ((const float4*)x)[i];
    __half2 h0 = __floats2half2_rn(v.x * r, v.y * r);
    __half2 h1 = __floats2half2_rn(v.z * r, v.w * r);
    ((uint2*)g_xs)[i] = make_uint2(*(unsigned*)&h0, *(unsigned*)&h1);
}

// ---- 3-phase exclusive scan of g_degin -> g_rowptr -------------------------
__global__ void scanA_kernel() {
    __shared__ int sh[1024];
    int idx = blockIdx.x * 1024 + threadIdx.x;
    sh[threadIdx.x] = (idx < NN) ? g_degin[idx] : 0;
    __syncthreads();
    for (int off = 512; off > 0; off >>= 1) {
        if (threadIdx.x < off) sh[threadIdx.x] += sh[threadIdx.x + off];
        __syncthreads();
    }
    if (threadIdx.x == 0) g_partial[blockIdx.x] = sh[0];
}

__global__ void scanB_kernel() {
    __shared__ int sh[128];
    int t = threadIdx.x;
    sh[t] = (t < NB) ? g_partial[t] : 0;
    __syncthreads();
    if (t == 0) {
        int run = 0;
        for (int b = 0; b < NB; b++) { int v = sh[b]; sh[b] = run; run += v; }
        g_rowptr[NN] = run;
    }
    __syncthreads();
    if (t < NB) g_base[t] = sh[t];
}

__global__ void scanC_kernel() {    // warp-shuffle scan
    __shared__ int warpsum[32];
    int tid = threadIdx.x;
    int idx = blockIdx.x * 1024 + tid;
    int lane = tid & 31, w = tid >> 5;
    int v = (idx < NN) ? g_degin[idx] : 0;
    int s = v;
    #pragma unroll
    for (int o = 1; o < 32; o <<= 1) {
        int t = __shfl_up_sync(0xffffffffu, s, o);
        if (lane >= o) s += t;
    }
    if (lane == 31) warpsum[w] = s;
    __syncthreads();
    if (w == 0) {
        int ws = warpsum[lane];
        #pragma unroll
        for (int o = 1; o < 32; o <<= 1) {
            int t = __shfl_up_sync(0xffffffffu, ws, o);
            if (lane >= o) ws += t;
        }
        warpsum[lane] = ws;
    }
    __syncthreads();
    int excl = s - v + (w > 0 ? warpsum[w - 1] : 0) + g_base[blockIdx.x];
    if (idx < NN) {
        g_rowptr[idx] = excl;
        g_cur[idx] = excl;
    }
}

__global__ void scatter_kernel(const int* __restrict__ src, const int* __restrict__ dst) {
    int e = blockIdx.x * blockDim.x + threadIdx.x;
    if (e < NE) {
        int pos = atomicAdd(&g_cur[dst[e]], 1);
        g_csrc[pos] = src[e];
    }
}

// ---- fused gather + FP16 double-GEMM ---------------------------------------
__device__ __forceinline__ unsigned smem_u32(const void* p) {
    return (unsigned)__cvta_generic_to_shared(p);
}
__device__ __forceinline__ void ldsm_x4(unsigned& r0, unsigned& r1, unsigned& r2, unsigned& r3,
                                        unsigned addr) {
    asm volatile("ldmatrix.sync.aligned.m8n8.x4.shared.b16 {%0,%1,%2,%3}, [%4];"
                 : "=r"(r0), "=r"(r1), "=r"(r2), "=r"(r3) : "r"(addr));
}
__device__ __forceinline__ void ldsm_x2t(unsigned& r0, unsigned& r1, unsigned addr) {
    asm volatile("ldmatrix.sync.aligned.m8n8.x2.trans.shared.b16 {%0,%1}, [%2];"
                 : "=r"(r0), "=r"(r1) : "r"(addr));
}
#define MMA_F16(c, a0, a1, a2, a3, b0, b1)                                    \
    asm volatile("mma.sync.aligned.m16n8k16.row.col.f32.f16.f16.f32 "         \
                 "{%0,%1,%2,%3}, {%4,%5,%6,%7}, {%8,%9}, {%0,%1,%2,%3};"      \
                 : "+f"(c[0]), "+f"(c[1]), "+f"(c[2]), "+f"(c[3])             \
                 : "r"(a0), "r"(a1), "r"(a2), "r"(a3), "r"(b0), "r"(b1))

#define AS_STRIDE 136
#define BS_STRIDE 72
#define OFF_AS  0
#define OFF_BS1 (64 * AS_STRIDE)
#define OFF_BS2 (OFF_BS1 + 128 * BS_STRIDE)
#define OFF_HS  (OFF_BS2 + 64 * BS_STRIDE)
#define FUSED_SMEM_HALVES (OFF_HS + 64 * BS_STRIDE)

__global__ void gemm_fused_kernel(const float* __restrict__ W1,  // [128,256]
                                  const float* __restrict__ W2,  // [256,64]
                                  const float* __restrict__ rin,
                                  const float* __restrict__ b1,
                                  const float* __restrict__ rout,
                                  __half* __restrict__ Cout,     // h2in [M,64]
                                  int M) {
    extern __shared__ __half sm[];
    __half* As  = sm + OFF_AS;
    __half* Bs1 = sm + OFF_BS1;
    __half* Bs2 = sm + OFF_BS2;
    __half* Hs  = sm + OFF_HS;

    int tid = threadIdx.x;
    int warp = tid >> 5, lane = tid & 31;
    int g = lane >> 2, q = lane & 3;
    int wm = warp & 1, wn = warp >> 1;
    int rowBase = blockIdx.x * 64;
    int l16 = lane & 15, lh = lane >> 4;

    float rs0[2], rs1[2], ro0[2], ro1[2];
    #pragma unroll
    for (int mt = 0; mt < 2; mt++) {
        int r = rowBase + wm * 32 + mt * 16 + g;
        rs0[mt] = (r < M) ? rin[r] : 0.f;
        ro0[mt] = (r < M) ? rout[r] : 0.f;
        rs1[mt] = (r + 8 < M) ? rin[r + 8] : 0.f;
        ro1[mt] = (r + 8 < M) ? rout[r + 8] : 0.f;
    }

    // phase 0: gather — warp w aggregates node rows 8w..8w+7 into As (fp16)
    #pragma unroll 1
    for (int rr = 0; rr < 8; rr++) {
        int row = warp * 8 + rr;
        int node = rowBase + row;
        float4 acc = make_float4(0.f, 0.f, 0.f, 0.f);
        if (node < M) {
            int beg = g_rowptr[node], end = g_rowptr[node + 1];
            int j = beg;
            for (; j + 3 < end; j += 4) {
                int s0 = g_csrc[j],     s1 = g_csrc[j + 1];
                int s2 = g_csrc[j + 2], s3 = g_csrc[j + 3];
                uint2 r0 = ((const uint2*)(g_xs + (size_t)s0 * 128))[lane];
                uint2 r1 = ((const uint2*)(g_xs + (size_t)s1 * 128))[lane];
                uint2 r2 = ((const uint2*)(g_xs + (size_t)s2 * 128))[lane];
                uint2 r3 = ((const uint2*)(g_xs + (size_t)s3 * 128))[lane];
                float2 a0 = __half22float2(*(__half2*)&r0.x), b0 = __half22float2(*(__half2*)&r0.y);
                float2 a1 = __half22float2(*(__half2*)&r1.x), b1v = __half22float2(*(__half2*)&r1.y);
                float2 a2 = __half22float2(*(__half2*)&r2.x), b2 = __half22float2(*(__half2*)&r2.y);
                float2 a3 = __half22float2(*(__half2*)&r3.x), b3 = __half22float2(*(__half2*)&r3.y);
                acc.x += a0.x + a1.x + a2.x + a3.x;
                acc.y += a0.y + a1.y + a2.y + a3.y;
                acc.z += b0.x + b1v.x + b2.x + b3.x;
                acc.w += b0.y + b1v.y + b2.y + b3.y;
            }
            for (; j < end; j++) {
                int s = g_csrc[j];
                uint2 r = ((const uint2*)(g_xs + (size_t)s * 128))[lane];
                float2 a = __half22float2(*(__half2*)&r.x), b = __half22float2(*(__half2*)&r.y);
                acc.x += a.x; acc.y += a.y; acc.z += b.x; acc.w += b.y;
            }
        }
        __half2 h0 = __floats2half2_rn(acc.x, acc.y);
        __half2 h1 = __floats2half2_rn(acc.z, acc.w);
        ((uint2*)(As + row * AS_STRIDE))[lane] = make_uint2(*(unsigned*)&h0, *(unsigned*)&h1);
    }

    float c2[2][2][4] = {};

    for (int qtr = 0; qtr < 4; qtr++) {
        // W1 tile: [128 k][64 n] fp32 -> fp16 Bs1
        #pragma unroll
        for (int it = 0; it < 8; it++) {
            int idx = tid + it * 256;
            int krow = idx >> 4;
            int c4 = (idx & 15) * 4;
            float4 v = *(const float4*)(W1 + (size_t)krow * 256 + qtr * 64 + c4);
            __half2 h0 = __floats2half2_rn(v.x, v.y);
            __half2 h1 = __floats2half2_rn(v.z, v.w);
            *(uint2*)(Bs1 + krow * BS_STRIDE + c4) = make_uint2(*(unsigned*)&h0, *(unsigned*)&h1);
        }
        __syncthreads();   // As (qtr 0) + Bs1 ready

        // MMA1: c1 = A_tile @ W1_quarter  (64x64, K=128)
        float c1[2][2][4] = {};
        #pragma unroll
        for (int ks = 0; ks < 8; ks++) {
            unsigned a[2][4], b[2][2];
            #pragma unroll
            for (int mt = 0; mt < 2; mt++)
                ldsm_x4(a[mt][0], a[mt][1], a[mt][2], a[mt][3],
                        smem_u32(As + (wm * 32 + mt * 16 + l16) * AS_STRIDE + ks * 16 + lh * 8));
            #pragma unroll
            for (int nt = 0; nt < 2; nt++)
                ldsm_x2t(b[nt][0], b[nt][1],
                         smem_u32(Bs1 + (ks * 16 + l16) * BS_STRIDE + wn * 16 + nt * 8));
            #pragma unroll
            for (int mt = 0; mt < 2; mt++)
                #pragma unroll
                for (int nt = 0; nt < 2; nt++)
                    MMA_F16(c1[mt][nt], a[mt][0], a[mt][1], a[mt][2], a[mt][3],
                            b[nt][0], b[nt][1]);
        }

        // epilogue1: relu(rin*c1 + b1) -> Hs fp16 [64 row][64 col]
        #pragma unroll
        for (int nt = 0; nt < 2; nt++) {
            int cL0 = wn * 16 + nt * 8 + 2 * q;
            float2 bb = *(const float2*)(b1 + qtr * 64 + cL0);
            #pragma unroll
            for (int mt = 0; mt < 2; mt++) {
                int r0 = wm * 32 + mt * 16 + g;
                __half2 h0 = __floats2half2_rn(fmaxf(c1[mt][nt][0] * rs0[mt] + bb.x, 0.f),
                                               fmaxf(c1[mt][nt][1] * rs0[mt] + bb.y, 0.f));
                __half2 h1 = __floats2half2_rn(fmaxf(c1[mt][nt][2] * rs1[mt] + bb.x, 0.f),
                                               fmaxf(c1[mt][nt][3] * rs1[mt] + bb.y, 0.f));
                *(__half2*)(Hs + r0 * BS_STRIDE + cL0) = h0;
                *(__half2*)(Hs + (r0 + 8) * BS_STRIDE + cL0) = h1;
            }
        }

        // W2 tile: rows qtr*64..+64 [64 k][64 n] -> fp16 Bs2
        #pragma unroll
        for (int it = 0; it < 4; it++) {
            int idx = tid + it * 256;
            int krow = idx >> 4;
            int c4 = (idx & 15) * 4;
            float4 v = *(const float4*)(W2 + (size_t)(qtr * 64 + krow) * 64 + c4);
            __half2 h0 = __floats2half2_rn(v.x, v.y);
            __half2 h1 = __floats2half2_rn(v.z, v.w);
            *(uint2*)(Bs2 + krow * BS_STRIDE + c4) = make_uint2(*(unsigned*)&h0, *(unsigned*)&h1);
        }
        __syncthreads();   // Hs + Bs2 ready

        // MMA2: c2 += h1_quarter @ W2_quarter  (64x64, K=64)
        #pragma unroll
        for (int ks = 0; ks < 4; ks++) {
            unsigned a[2][4], b[2][2];
            #pragma unroll
            for (int mt = 0; mt < 2; mt++)
                ldsm_x4(a[mt][0], a[mt][1], a[mt][2], a[mt][3],
                        smem_u32(Hs + (wm * 32 + mt * 16 + l16) * BS_STRIDE + ks * 16 + lh * 8));
            #pragma unroll
            for (int nt = 0; nt < 2; nt++)
                ldsm_x2t(b[nt][0], b[nt][1],
                         smem_u32(Bs2 + (ks * 16 + l16) * BS_STRIDE + wn * 16 + nt * 8));
            #pragma unroll
            for (int mt = 0; mt < 2; mt++)
                #pragma unroll
                for (int nt = 0; nt < 2; nt++)
                    MMA_F16(c2[mt][nt], a[mt][0], a[mt][1], a[mt][2], a[mt][3],
                            b[nt][0], b[nt][1]);
        }
        __syncthreads();   // all MMA2 reads done before next quarter's writes
    }

    // final epilogue: h2in = fp16(rout * c2)
    #pragma unroll
    for (int mt = 0; mt < 2; mt++) {
        int r0 = rowBase + wm * 32 + mt * 16 + g;
        #pragma unroll
        for (int nt = 0; nt < 2; nt++) {
            int c0 = wn * 16 + nt * 8 + 2 * q;
            if (r0 < M)
                *(__half2*)(Cout + (size_t)r0 * 64 + c0) =
                    __floats2half2_rn(c2[mt][nt][0] * ro0[mt], c2[mt][nt][1] * ro0[mt]);
            if (r0 + 8 < M)
                *(__half2*)(Cout + (size_t)(r0 + 8) * 64 + c0) =
                    __floats2half2_rn(c2[mt][nt][2] * ro1[mt], c2[mt][nt][3] * ro1[mt]);
        }
    }
}

// ---- layer-2 aggregation fused with mean-pool reduction (fp16 gather) ------
__global__ void agg2_pool_kernel(const int* __restrict__ gid, const float* __restrict__ b2) {
    __shared__ float sv[8][64];
    __shared__ int sg[8];
    int wid = threadIdx.x >> 5, lane = threadIdx.x & 31;
    int node = blockIdx.x * 8 + wid;
    float2 acc = make_float2(0.f, 0.f);
    int gv = -1;
    if (node < NN) {
        int beg = g_rowptr[node], end = g_rowptr[node + 1];
        int j = beg;
        for (; j + 3 < end; j += 4) {
            int s0 = g_csrc[j],     s1 = g_csrc[j + 1];
            int s2 = g_csrc[j + 2], s3 = g_csrc[j + 3];
            float2 v0 = __half22float2(((const __half2*)(g_h2in + (size_t)s0 * 64))[lane]);
            float2 v1 = __half22float2(((const __half2*)(g_h2in + (size_t)s1 * 64))[lane]);
            float2 v2 = __half22float2(((const __half2*)(g_h2in + (size_t)s2 * 64))[lane]);
            float2 v3 = __half22float2(((const __half2*)(g_h2in + (size_t)s3 * 64))[lane]);
            acc.x += v0.x + v1.x + v2.x + v3.x;
            acc.y += v0.y + v1.y + v2.y + v3.y;
        }
        for (; j < end; j++) {
            int s = g_csrc[j];
            float2 v = __half22float2(((const __half2*)(g_h2in + (size_t)s * 64))[lane]);
            acc.x += v.x; acc.y += v.y;
        }
        float ri = g_rin[node];
        float2 bb = ((const float2*)b2)[lane];
        acc.x = fmaxf(acc.x * ri + bb.x, 0.f);
        acc.y = fmaxf(acc.y * ri + bb.y, 0.f);
        gv = gid[node];
    }
    sv[wid][lane * 2]     = acc.x;
    sv[wid][lane * 2 + 1] = acc.y;
    if (lane == 0) sg[wid] = gv;
    __syncthreads();

    if (wid == 0) {
        int c0 = lane * 2;
        float a0 = 0.f, a1 = 0.f;
        int cnt = 0;
        int cur = sg[0];
        #pragma unroll
        for (int w = 0; w < 8; w++) {
            int gw = sg[w];
            if (gw != cur) {
                if (cur >= 0) {
                    atomicAdd(&g_gsum[cur * 64 + c0], a0);
                    atomicAdd(&g_gsum[cur * 64 + c0 + 1], a1);
                    if (lane == 0) atomicAdd(&g_gcnt[cur], cnt);
                }
                a0 = 0.f; a1 = 0.f; cnt = 0; cur = gw;
            }
            if (gw >= 0) { a0 += sv[w][c0]; a1 += sv[w][c0 + 1]; cnt++; }
        }
        if (cur >= 0) {
            atomicAdd(&g_gsum[cur * 64 + c0], a0);
            atomicAdd(&g_gsum[cur * 64 + c0 + 1], a1);
            if (lane == 0) atomicAdd(&g_gcnt[cur], cnt);
        }
    }
}

__global__ void classifier_kernel(const float* __restrict__ Wc1, const float* __restrict__ bc1,
                                  const float* __restrict__ Wc2, const float* __restrict__ bc2,
                                  const float* __restrict__ Wc3, const float* __restrict__ bc3,
                                  const float* __restrict__ Wc4, const float* __restrict__ bc4,
                                  float* __restrict__ out) {
    int g = blockIdx.x * blockDim.x + threadIdx.x;
    if (g >= NG) return;
    float inv = 1.f / fmaxf((float)g_gcnt[g], 1.f);
    float h[64];
    #pragma unroll
    for (int j = 0; j < 64; j++) h[j] = g_gsum[g * 64 + j] * inv;
    float t1[18];
    for (int j = 0; j < 18; j++) {
        float s = bc1[j];
        for (int k = 0; k < 64; k++) s += h[k] * Wc1[k * 18 + j];
        t1[j] = s;
    }
    float t2[12];
    for (int j = 0; j < 12; j++) {
        float s = bc2[j];
        for (int k = 0; k < 18; k++) s += t1[k] * Wc2[k * 12 + j];
        t2[j] = s;
    }
    float t3[6];
    for (int j = 0; j < 6; j++) {
        float s = bc3[j];
        for (int k = 0; k < 12; k++) s += t2[k] * Wc3[k * 6 + j];
        t3[j] = s;
    }
    for (int j = 0; j < 2; j++) {
        float s = bc4[j];
        for (int k = 0; k < 6; k++) s += t3[k] * Wc4[k * 2 + j];
        out[g * 2 + j] = s;
    }
}

// ---------------------------------------------------------------------------
extern "C" void kernel_launch(void* const* d_in, const int* in_sizes, int n_in,
                              void* d_out, int out_size) {
    const float* x   = (const float*)d_in[0];
    const int*   src = (const int*)d_in[1];
    const int*   dst = (const int*)d_in[2];
    const int*   gid = (const int*)d_in[3];
    const float* W1  = (const float*)d_in[4];
    const float* b1  = (const float*)d_in[5];
    const float* W2  = (const float*)d_in[6];
    const float* b2  = (const float*)d_in[7];
    const float* Wc1 = (const float*)d_in[8];
    const float* bc1 = (const float*)d_in[9];
    const float* Wc2 = (const float*)d_in[10];
    const float* bc2 = (const float*)d_in[11];
    const float* Wc3 = (const float*)d_in[12];
    const float* bc3 = (const float*)d_in[13];
    const float* Wc4 = (const float*)d_in[14];
    const float* bc4 = (const float*)d_in[15];
    float* out = (float*)d_out;

    float *p_rin, *p_rout;
    __half* p_h2in;
    cudaGetSymbolAddress((void**)&p_h2in, g_h2in);
    cudaGetSymbolAddress((void**)&p_rin,  g_rin);
    cudaGetSymbolAddress((void**)&p_rout, g_rout);

    static int smem_set = 0;
    const int fused_smem = FUSED_SMEM_HALVES * 2;
    if (!smem_set) {
        cudaFuncSetAttribute(gemm_fused_kernel,
                             cudaFuncAttributeMaxDynamicSharedMemorySize, fused_smem);
        smem_set = 1;
    }

    zero_small_kernel<<<256, 256>>>();
    degree_kernel<<<(NE + 255) / 256, 256>>>(src, dst);

    // pre-scale + fp16 pack x (also computes g_rout / g_rin inline)
    xscale_kernel<<<(NN * 32 + 255) / 256, 256>>>(x);

    // CSR build (dst-major)
    scanA_kernel<<<NB, 1024>>>();
    scanB_kernel<<<1, 128>>>();
    scanC_kernel<<<NB, 1024>>>();
    scatter_kernel<<<(NE + 255) / 256, 256>>>(src, dst);

    // fused gather + fp16 tensor-core double GEMM
    gemm_fused_kernel<<<(NN + 63) / 64, 256, fused_smem>>>(
        W1, W2, p_rin, b1, p_rout, p_h2in, NN);

    // layer 2 gather + pool (fp16 gather)
    agg2_pool_kernel<<<(NN + 7) / 8, 256>>>(gid, b2);

    classifier_kernel<<<(NG + 255) / 256, 256>>>(Wc1, bc1, Wc2, bc2, Wc3, bc3, Wc4, bc4, out);
}

// round 16
// speedup vs baseline: 1.3822x; 1.3822x over previous
#include <cuda_runtime.h>
#include <cuda_fp16.h>

#define NN 100000
#define NE 1600000
#define NG 512
#define NB 98   // ceil(NN/1024)

// ---- scratch (device globals; no allocation allowed) ----
__device__ int    g_degout[NN];
__device__ int    g_degin[NN];
__device__ float  g_rout[NN];
__device__ float  g_rin[NN];
__device__ int    g_rowptr[NN + 1];
__device__ int    g_cur[NN];
__device__ int    g_partial[NB];
__device__ int    g_base[NB];
__device__ int    g_csrc[NE];
__device__ __half g_xs[NN * 128];     // fp16(x * rout), 25.6 MB
__device__ __half g_h2in[NN * 64];    // 12.8 MB
__device__ float  g_gsum[NG * 64];
__device__ int    g_gcnt[NG];

// ---------------------------------------------------------------------------
__global__ void zero_small_kernel() {
    int i = blockIdx.x * blockDim.x + threadIdx.x;
    int stride = gridDim.x * blockDim.x;
    for (int j = i; j < NN; j += stride) { g_degout[j] = 0; g_degin[j] = 0; }
    for (int j = i; j < NG * 64; j += stride) g_gsum[j] = 0.f;
    for (int j = i; j < NG; j += stride) g_gcnt[j] = 0;
}

__global__ void degree_kernel(const int* __restrict__ src, const int* __restrict__ dst) {
    int e = blockIdx.x * blockDim.x + threadIdx.x;
    if (e < NE) {
        atomicAdd(&g_degout[src[e]], 1);
        atomicAdd(&g_degin[dst[e]], 1);
    }
}

__global__ void finalize_deg_kernel() {
    int i = blockIdx.x * blockDim.x + threadIdx.x;
    if (i < NN) {
        g_rout[i] = rsqrtf((float)max(g_degout[i], 1));
        g_rin[i]  = rsqrtf((float)max(g_degin[i], 1));
    }
}

// xs[n][d] = fp16( x[n][d] * rout[n] )
__global__ void xscale_kernel(const float* __restrict__ x) {
    int i = blockIdx.x * blockDim.x + threadIdx.x;   // float4 index
    int total = NN * 128 / 4;
    if (i >= total) return;
    int node = i >> 5;
    float r = g_rout[node];
    float4 v = ((const float4*)x)[i];
    __half2 h0 = __floats2half2_rn(v.x * r, v.y * r);
    __half2 h1 = __floats2half2_rn(v.z * r, v.w * r);
    ((uint2*)g_xs)[i] = make_uint2(*(unsigned*)&h0, *(unsigned*)&h1);
}

// ---- 3-phase exclusive scan of g_degin -> g_rowptr -------------------------
__global__ void scanA_kernel() {
    __shared__ int sh[1024];
    int idx = blockIdx.x * 1024 + threadIdx.x;
    sh[threadIdx.x] = (idx < NN) ? g_degin[idx] : 0;
    __syncthreads();
    for (int off = 512; off > 0; off >>= 1) {
        if (threadIdx.x < off) sh[threadIdx.x] += sh[threadIdx.x + off];
        __syncthreads();
    }
    if (threadIdx.x == 0) g_partial[blockIdx.x] = sh[0];
}

__global__ void scanB_kernel() {
    __shared__ int sh[128];
    int t = threadIdx.x;
    sh[t] = (t < NB) ? g_partial[t] : 0;
    __syncthreads();
    if (t == 0) {
        int run = 0;
        for (int b = 0; b < NB; b++) { int v = sh[b]; sh[b] = run; run += v; }
        g_rowptr[NN] = run;
    }
    __syncthreads();
    if (t < NB) g_base[t] = sh[t];
}

__global__ void scanC_kernel() {    // warp-shuffle scan
    __shared__ int warpsum[32];
    int tid = threadIdx.x;
    int idx = blockIdx.x * 1024 + tid;
    int lane = tid & 31, w = tid >> 5;
    int v = (idx < NN) ? g_degin[idx] : 0;
    int s = v;
    #pragma unroll
    for (int o = 1; o < 32; o <<= 1) {
        int t = __shfl_up_sync(0xffffffffu, s, o);
        if (lane >= o) s += t;
    }
    if (lane == 31) warpsum[w] = s;
    __syncthreads();
    if (w == 0) {
        int ws = warpsum[lane];
        #pragma unroll
        for (int o = 1; o < 32; o <<= 1) {
            int t = __shfl_up_sync(0xffffffffu, ws, o);
            if (lane >= o) ws += t;
        }
        warpsum[lane] = ws;
    }
    __syncthreads();
    int excl = s - v + (w > 0 ? warpsum[w - 1] : 0) + g_base[blockIdx.x];
    if (idx < NN) {
        g_rowptr[idx] = excl;
        g_cur[idx] = excl;
    }
}

__global__ void scatter_kernel(const int* __restrict__ src, const int* __restrict__ dst) {
    int e = blockIdx.x * blockDim.x + threadIdx.x;
    if (e < NE) {
        int pos = atomicAdd(&g_cur[dst[e]], 1);
        g_csrc[pos] = src[e];
    }
}

// ---- fused gather + FP16 double-GEMM ---------------------------------------
// As = segsum over in-edges of xs (gathered in-kernel, fp32 acc -> fp16 smem)
// h2in = fp16( rout ⊙ ( relu( rin ⊙ (As @ W1) + b1 ) @ W2 ) )
__device__ __forceinline__ unsigned smem_u32(const void* p) {
    return (unsigned)__cvta_generic_to_shared(p);
}
__device__ __forceinline__ void ldsm_x4(unsigned& r0, unsigned& r1, unsigned& r2, unsigned& r3,
                                        unsigned addr) {
    asm volatile("ldmatrix.sync.aligned.m8n8.x4.shared.b16 {%0,%1,%2,%3}, [%4];"
                 : "=r"(r0), "=r"(r1), "=r"(r2), "=r"(r3) : "r"(addr));
}
__device__ __forceinline__ void ldsm_x2t(unsigned& r0, unsigned& r1, unsigned addr) {
    asm volatile("ldmatrix.sync.aligned.m8n8.x2.trans.shared.b16 {%0,%1}, [%2];"
                 : "=r"(r0), "=r"(r1) : "r"(addr));
}
#define MMA_F16(c, a0, a1, a2, a3, b0, b1)                                    \
    asm volatile("mma.sync.aligned.m16n8k16.row.col.f32.f16.f16.f32 "         \
                 "{%0,%1,%2,%3}, {%4,%5,%6,%7}, {%8,%9}, {%0,%1,%2,%3};"      \
                 : "+f"(c[0]), "+f"(c[1]), "+f"(c[2]), "+f"(c[3])             \
                 : "r"(a0), "r"(a1), "r"(a2), "r"(a3), "r"(b0), "r"(b1))

#define AS_STRIDE 136
#define BS_STRIDE 72
#define OFF_AS  0
#define OFF_BS1 (64 * AS_STRIDE)
#define OFF_BS2 (OFF_BS1 + 128 * BS_STRIDE)
#define OFF_HS  (OFF_BS2 + 64 * BS_STRIDE)
#define FUSED_SMEM_HALVES (OFF_HS + 64 * BS_STRIDE)

__global__ void gemm_fused_kernel(const float* __restrict__ W1,  // [128,256]
                                  const float* __restrict__ W2,  // [256,64]
                                  const float* __restrict__ rin,
                                  const float* __restrict__ b1,
                                  const float* __restrict__ rout,
                                  __half* __restrict__ Cout,     // h2in [M,64]
                                  int M) {
    extern __shared__ __half sm[];
    __half* As  = sm + OFF_AS;
    __half* Bs1 = sm + OFF_BS1;
    __half* Bs2 = sm + OFF_BS2;
    __half* Hs  = sm + OFF_HS;

    int tid = threadIdx.x;
    int warp = tid >> 5, lane = tid & 31;
    int g = lane >> 2, q = lane & 3;
    int wm = warp & 1, wn = warp >> 1;
    int rowBase = blockIdx.x * 64;
    int l16 = lane & 15, lh = lane >> 4;

    float rs0[2], rs1[2], ro0[2], ro1[2];
    #pragma unroll
    for (int mt = 0; mt < 2; mt++) {
        int r = rowBase + wm * 32 + mt * 16 + g;
        rs0[mt] = (r < M) ? rin[r] : 0.f;
        ro0[mt] = (r < M) ? rout[r] : 0.f;
        rs1[mt] = (r + 8 < M) ? rin[r + 8] : 0.f;
        ro1[mt] = (r + 8 < M) ? rout[r + 8] : 0.f;
    }

    // phase 0: gather — warp w aggregates node rows 8w..8w+7 into As (fp16)
    #pragma unroll 1
    for (int rr = 0; rr < 8; rr++) {
        int row = warp * 8 + rr;
        int node = rowBase + row;
        float4 acc = make_float4(0.f, 0.f, 0.f, 0.f);
        if (node < M) {
            int beg = g_rowptr[node], end = g_rowptr[node + 1];
            int j = beg;
            for (; j + 3 < end; j += 4) {
                int s0 = g_csrc[j],     s1 = g_csrc[j + 1];
                int s2 = g_csrc[j + 2], s3 = g_csrc[j + 3];
                uint2 r0 = ((const uint2*)(g_xs + (size_t)s0 * 128))[lane];
                uint2 r1 = ((const uint2*)(g_xs + (size_t)s1 * 128))[lane];
                uint2 r2 = ((const uint2*)(g_xs + (size_t)s2 * 128))[lane];
                uint2 r3 = ((const uint2*)(g_xs + (size_t)s3 * 128))[lane];
                float2 a0 = __half22float2(*(__half2*)&r0.x), b0 = __half22float2(*(__half2*)&r0.y);
                float2 a1 = __half22float2(*(__half2*)&r1.x), b1v = __half22float2(*(__half2*)&r1.y);
                float2 a2 = __half22float2(*(__half2*)&r2.x), b2 = __half22float2(*(__half2*)&r2.y);
                float2 a3 = __half22float2(*(__half2*)&r3.x), b3 = __half22float2(*(__half2*)&r3.y);
                acc.x += a0.x + a1.x + a2.x + a3.x;
                acc.y += a0.y + a1.y + a2.y + a3.y;
                acc.z += b0.x + b1v.x + b2.x + b3.x;
                acc.w += b0.y + b1v.y + b2.y + b3.y;
            }
            for (; j < end; j++) {
                int s = g_csrc[j];
                uint2 r = ((const uint2*)(g_xs + (size_t)s * 128))[lane];
                float2 a = __half22float2(*(__half2*)&r.x), b = __half22float2(*(__half2*)&r.y);
                acc.x += a.x; acc.y += a.y; acc.z += b.x; acc.w += b.y;
            }
        }
        __half2 h0 = __floats2half2_rn(acc.x, acc.y);
        __half2 h1 = __floats2half2_rn(acc.z, acc.w);
        ((uint2*)(As + row * AS_STRIDE))[lane] = make_uint2(*(unsigned*)&h0, *(unsigned*)&h1);
    }

    float c2[2][2][4] = {};

    for (int qtr = 0; qtr < 4; qtr++) {
        // W1 tile: [128 k][64 n] fp32 -> fp16 Bs1
        #pragma unroll
        for (int it = 0; it < 8; it++) {
            int idx = tid + it * 256;
            int krow = idx >> 4;
            int c4 = (idx & 15) * 4;
            float4 v = *(const float4*)(W1 + (size_t)krow * 256 + qtr * 64 + c4);
            __half2 h0 = __floats2half2_rn(v.x, v.y);
            __half2 h1 = __floats2half2_rn(v.z, v.w);
            *(uint2*)(Bs1 + krow * BS_STRIDE + c4) = make_uint2(*(unsigned*)&h0, *(unsigned*)&h1);
        }
        __syncthreads();   // As (qtr 0) + Bs1 ready

        // MMA1: c1 = A_tile @ W1_quarter  (64x64, K=128)
        float c1[2][2][4] = {};
        #pragma unroll
        for (int ks = 0; ks < 8; ks++) {
            unsigned a[2][4], b[2][2];
            #pragma unroll
            for (int mt = 0; mt < 2; mt++)
                ldsm_x4(a[mt][0], a[mt][1], a[mt][2], a[mt][3],
                        smem_u32(As + (wm * 32 + mt * 16 + l16) * AS_STRIDE + ks * 16 + lh * 8));
            #pragma unroll
            for (int nt = 0; nt < 2; nt++)
                ldsm_x2t(b[nt][0], b[nt][1],
                         smem_u32(Bs1 + (ks * 16 + l16) * BS_STRIDE + wn * 16 + nt * 8));
            #pragma unroll
            for (int mt = 0; mt < 2; mt++)
                #pragma unroll
                for (int nt = 0; nt < 2; nt++)
                    MMA_F16(c1[mt][nt], a[mt][0], a[mt][1], a[mt][2], a[mt][3],
                            b[nt][0], b[nt][1]);
        }

        // epilogue1: relu(rin*c1 + b1) -> Hs fp16 [64 row][64 col]
        #pragma unroll
        for (int nt = 0; nt < 2; nt++) {
            int cL0 = wn * 16 + nt * 8 + 2 * q;
            float2 bb = *(const float2*)(b1 + qtr * 64 + cL0);
            #pragma unroll
            for (int mt = 0; mt < 2; mt++) {
                int r0 = wm * 32 + mt * 16 + g;
                __half2 h0 = __floats2half2_rn(fmaxf(c1[mt][nt][0] * rs0[mt] + bb.x, 0.f),
                                               fmaxf(c1[mt][nt][1] * rs0[mt] + bb.y, 0.f));
                __half2 h1 = __floats2half2_rn(fmaxf(c1[mt][nt][2] * rs1[mt] + bb.x, 0.f),
                                               fmaxf(c1[mt][nt][3] * rs1[mt] + bb.y, 0.f));
                *(__half2*)(Hs + r0 * BS_STRIDE + cL0) = h0;
                *(__half2*)(Hs + (r0 + 8) * BS_STRIDE + cL0) = h1;
            }
        }

        // W2 tile: rows qtr*64..+64 [64 k][64 n] -> fp16 Bs2
        #pragma unroll
        for (int it = 0; it < 4; it++) {
            int idx = tid + it * 256;
            int krow = idx >> 4;
            int c4 = (idx & 15) * 4;
            float4 v = *(const float4*)(W2 + (size_t)(qtr * 64 + krow) * 64 + c4);
            __half2 h0 = __floats2half2_rn(v.x, v.y);
            __half2 h1 = __floats2half2_rn(v.z, v.w);
            *(uint2*)(Bs2 + krow * BS_STRIDE + c4) = make_uint2(*(unsigned*)&h0, *(unsigned*)&h1);
        }
        __syncthreads();   // Hs + Bs2 ready

        // MMA2: c2 += h1_quarter @ W2_quarter  (64x64, K=64)
        #pragma unroll
        for (int ks = 0; ks < 4; ks++) {
            unsigned a[2][4], b[2][2];
            #pragma unroll
            for (int mt = 0; mt < 2; mt++)
                ldsm_x4(a[mt][0], a[mt][1], a[mt][2], a[mt][3],
                        smem_u32(Hs + (wm * 32 + mt * 16 + l16) * BS_STRIDE + ks * 16 + lh * 8));
            #pragma unroll
            for (int nt = 0; nt < 2; nt++)
                ldsm_x2t(b[nt][0], b[nt][1],
                         smem_u32(Bs2 + (ks * 16 + l16) * BS_STRIDE + wn * 16 + nt * 8));
            #pragma unroll
            for (int mt = 0; mt < 2; mt++)
                #pragma unroll
                for (int nt = 0; nt < 2; nt++)
                    MMA_F16(c2[mt][nt], a[mt][0], a[mt][1], a[mt][2], a[mt][3],
                            b[nt][0], b[nt][1]);
        }
        __syncthreads();   // all MMA2 reads done before next quarter's writes
    }

    // final epilogue: h2in = fp16(rout * c2)
    #pragma unroll
    for (int mt = 0; mt < 2; mt++) {
        int r0 = rowBase + wm * 32 + mt * 16 + g;
        #pragma unroll
        for (int nt = 0; nt < 2; nt++) {
            int c0 = wn * 16 + nt * 8 + 2 * q;
            if (r0 < M)
                *(__half2*)(Cout + (size_t)r0 * 64 + c0) =
                    __floats2half2_rn(c2[mt][nt][0] * ro0[mt], c2[mt][nt][1] * ro0[mt]);
            if (r0 + 8 < M)
                *(__half2*)(Cout + (size_t)(r0 + 8) * 64 + c0) =
                    __floats2half2_rn(c2[mt][nt][2] * ro1[mt], c2[mt][nt][3] * ro1[mt]);
        }
    }
}

// ---- layer-2 aggregation fused with mean-pool reduction (fp16 gather) ------
__global__ void agg2_pool_kernel(const int* __restrict__ gid, const float* __restrict__ b2) {
    __shared__ float sv[8][64];
    __shared__ int sg[8];
    int wid = threadIdx.x >> 5, lane = threadIdx.x & 31;
    int node = blockIdx.x * 8 + wid;
    float2 acc = make_float2(0.f, 0.f);
    int gv = -1;
    if (node < NN) {
        int beg = g_rowptr[node], end = g_rowptr[node + 1];
        int j = beg;
        for (; j + 3 < end; j += 4) {
            int s0 = g_csrc[j],     s1 = g_csrc[j + 1];
            int s2 = g_csrc[j + 2], s3 = g_csrc[j + 3];
            float2 v0 = __half22float2(((const __half2*)(g_h2in + (size_t)s0 * 64))[lane]);
            float2 v1 = __half22float2(((const __half2*)(g_h2in + (size_t)s1 * 64))[lane]);
            float2 v2 = __half22float2(((const __half2*)(g_h2in + (size_t)s2 * 64))[lane]);
            float2 v3 = __half22float2(((const __half2*)(g_h2in + (size_t)s3 * 64))[lane]);
            acc.x += v0.x + v1.x + v2.x + v3.x;
            acc.y += v0.y + v1.y + v2.y + v3.y;
        }
        for (; j < end; j++) {
            int s = g_csrc[j];
            float2 v = __half22float2(((const __half2*)(g_h2in + (size_t)s * 64))[lane]);
            acc.x += v.x; acc.y += v.y;
        }
        float ri = g_rin[node];
        float2 bb = ((const float2*)b2)[lane];
        acc.x = fmaxf(acc.x * ri + bb.x, 0.f);
        acc.y = fmaxf(acc.y * ri + bb.y, 0.f);
        gv = gid[node];
    }
    sv[wid][lane * 2]     = acc.x;
    sv[wid][lane * 2 + 1] = acc.y;
    if (lane == 0) sg[wid] = gv;
    __syncthreads();

    if (wid == 0) {
        int c0 = lane * 2;
        float a0 = 0.f, a1 = 0.f;
        int cnt = 0;
        int cur = sg[0];
        #pragma unroll
        for (int w = 0; w < 8; w++) {
            int gw = sg[w];
            if (gw != cur) {
                if (cur >= 0) {
                    atomicAdd(&g_gsum[cur * 64 + c0], a0);
                    atomicAdd(&g_gsum[cur * 64 + c0 + 1], a1);
                    if (lane == 0) atomicAdd(&g_gcnt[cur], cnt);
                }
                a0 = 0.f; a1 = 0.f; cnt = 0; cur = gw;
            }
            if (gw >= 0) { a0 += sv[w][c0]; a1 += sv[w][c0 + 1]; cnt++; }
        }
        if (cur >= 0) {
            atomicAdd(&g_gsum[cur * 64 + c0], a0);
            atomicAdd(&g_gsum[cur * 64 + c0 + 1], a1);
            if (lane == 0) atomicAdd(&g_gcnt[cur], cnt);
        }
    }
}

__global__ void classifier_kernel(const float* __restrict__ Wc1, const float* __restrict__ bc1,
                                  const float* __restrict__ Wc2, const float* __restrict__ bc2,
                                  const float* __restrict__ Wc3, const float* __restrict__ bc3,
                                  const float* __restrict__ Wc4, const float* __restrict__ bc4,
                                  float* __restrict__ out) {
    int g = blockIdx.x * blockDim.x + threadIdx.x;
    if (g >= NG) return;
    float inv = 1.f / fmaxf((float)g_gcnt[g], 1.f);
    float h[64];
    #pragma unroll
    for (int j = 0; j < 64; j++) h[j] = g_gsum[g * 64 + j] * inv;
    float t1[18];
    for (int j = 0; j < 18; j++) {
        float s = bc1[j];
        for (int k = 0; k < 64; k++) s += h[k] * Wc1[k * 18 + j];
        t1[j] = s;
    }
    float t2[12];
    for (int j = 0; j < 12; j++) {
        float s = bc2[j];
        for (int k = 0; k < 18; k++) s += t1[k] * Wc2[k * 12 + j];
        t2[j] = s;
    }
    float t3[6];
    for (int j = 0; j < 6; j++) {
        float s = bc3[j];
        for (int k = 0; k < 12; k++) s += t2[k] * Wc3[k * 6 + j];
        t3[j] = s;
    }
    for (int j = 0; j < 2; j++) {
        float s = bc4[j];
        for (int k = 0; k < 6; k++) s += t3[k] * Wc4[k * 2 + j];
        out[g * 2 + j] = s;
    }
}

// ---------------------------------------------------------------------------
extern "C" void kernel_launch(void* const* d_in, const int* in_sizes, int n_in,
                              void* d_out, int out_size) {
    const float* x   = (const float*)d_in[0];
    const int*   src = (const int*)d_in[1];
    const int*   dst = (const int*)d_in[2];
    const int*   gid = (const int*)d_in[3];
    const float* W1  = (const float*)d_in[4];
    const float* b1  = (const float*)d_in[5];
    const float* W2  = (const float*)d_in[6];
    const float* b2  = (const float*)d_in[7];
    const float* Wc1 = (const float*)d_in[8];
    const float* bc1 = (const float*)d_in[9];
    const float* Wc2 = (const float*)d_in[10];
    const float* bc2 = (const float*)d_in[11];
    const float* Wc3 = (const float*)d_in[12];
    const float* bc3 = (const float*)d_in[13];
    const float* Wc4 = (const float*)d_in[14];
    const float* bc4 = (const float*)d_in[15];
    float* out = (float*)d_out;

    float *p_rin, *p_rout;
    __half* p_h2in;
    cudaGetSymbolAddress((void**)&p_h2in, g_h2in);
    cudaGetSymbolAddress((void**)&p_rin,  g_rin);
    cudaGetSymbolAddress((void**)&p_rout, g_rout);

    static int smem_set = 0;
    const int fused_smem = FUSED_SMEM_HALVES * 2;
    if (!smem_set) {
        cudaFuncSetAttribute(gemm_fused_kernel,
                             cudaFuncAttributeMaxDynamicSharedMemorySize, fused_smem);
        smem_set = 1;
    }

    zero_small_kernel<<<256, 256>>>();
    degree_kernel<<<(NE + 255) / 256, 256>>>(src, dst);
    finalize_deg_kernel<<<(NN + 255) / 256, 256>>>();

    // pre-scale + fp16 pack x
    xscale_kernel<<<(NN * 32 + 255) / 256, 256>>>(x);

    // CSR build (dst-major)
    scanA_kernel<<<NB, 1024>>>();
    scanB_kernel<<<1, 128>>>();
    scanC_kernel<<<NB, 1024>>>();
    scatter_kernel<<<(NE + 255) / 256, 256>>>(src, dst);

    // fused gather + fp16 tensor-core double GEMM
    gemm_fused_kernel<<<(NN + 63) / 64, 256, fused_smem>>>(
        W1, W2, p_rin, b1, p_rout, p_h2in, NN);

    // layer 2 gather + pool (fp16 gather)
    agg2_pool_kernel<<<(NN + 7) / 8, 256>>>(gid, b2);

    classifier_kernel<<<(NG + 255) / 256, 256>>>(Wc1, bc1, Wc2, bc2, Wc3, bc3, Wc4, bc4, out);
}

// round 17
// speedup vs baseline: 1.4047x; 1.0163x over previous
#include <cuda_runtime.h>
#include <cuda_fp16.h>

#define NN 100000
#define NE 1600000
#define NG 512
#define NB 98   // ceil(NN/1024)

// ---- scratch (device globals; no allocation allowed) ----
__device__ int    g_degout[NN];
__device__ int    g_degin[NN];
__device__ float  g_rout[NN];
__device__ float  g_rin[NN];
__device__ int    g_rowptr[NN + 1];
__device__ int    g_cur[NN];
__device__ int    g_partial[NB];
__device__ int    g_base[NB];
__device__ int    g_csrc[NE];
__device__ __half g_xs[NN * 128];     // fp16(x * rout), 25.6 MB
__device__ __half g_W1h[128 * 256];   // fp16 W1
__device__ __half g_W2h[256 * 64];    // fp16 W2
__device__ __half g_h2in[NN * 64];    // 12.8 MB
__device__ float  g_gsum[NG * 64];
__device__ int    g_gcnt[NG];

// ---------------------------------------------------------------------------
// zero scratch + one-shot fp16 weight pack (same __floats2half2_rn rounding
// the fused kernel used per-CTA, so results are bit-identical)
__global__ void zero_wpack_kernel(const float* __restrict__ W1, const float* __restrict__ W2) {
    int i = blockIdx.x * blockDim.x + threadIdx.x;
    int stride = gridDim.x * blockDim.x;
    for (int j = i; j < NN; j += stride) { g_degout[j] = 0; g_degin[j] = 0; }
    for (int j = i; j < NG * 64; j += stride) g_gsum[j] = 0.f;
    for (int j = i; j < NG; j += stride) g_gcnt[j] = 0;
    const int n1 = 128 * 256 / 2;   // half2 count
    const int n2 = 256 * 64 / 2;
    for (int j = i; j < n1; j += stride) {
        float2 v = ((const float2*)W1)[j];
        ((__half2*)g_W1h)[j] = __floats2half2_rn(v.x, v.y);
    }
    for (int j = i; j < n2; j += stride) {
        float2 v = ((const float2*)W2)[j];
        ((__half2*)g_W2h)[j] = __floats2half2_rn(v.x, v.y);
    }
}

__global__ void degree_kernel(const int* __restrict__ src, const int* __restrict__ dst) {
    int e = blockIdx.x * blockDim.x + threadIdx.x;
    if (e < NE) {
        atomicAdd(&g_degout[src[e]], 1);
        atomicAdd(&g_degin[dst[e]], 1);
    }
}

__global__ void finalize_deg_kernel() {
    int i = blockIdx.x * blockDim.x + threadIdx.x;
    if (i < NN) {
        g_rout[i] = rsqrtf((float)max(g_degout[i], 1));
        g_rin[i]  = rsqrtf((float)max(g_degin[i], 1));
    }
}

// xs[n][d] = fp16( x[n][d] * rout[n] )
__global__ void xscale_kernel(const float* __restrict__ x) {
    int i = blockIdx.x * blockDim.x + threadIdx.x;   // float4 index
    int total = NN * 128 / 4;
    if (i >= total) return;
    int node = i >> 5;
    float r = g_rout[node];
    float4 v = ((const float4*)x)[i];
    __half2 h0 = __floats2half2_rn(v.x * r, v.y * r);
    __half2 h1 = __floats2half2_rn(v.z * r, v.w * r);
    ((uint2*)g_xs)[i] = make_uint2(*(unsigned*)&h0, *(unsigned*)&h1);
}

// ---- 3-phase exclusive scan of g_degin -> g_rowptr -------------------------
__global__ void scanA_kernel() {
    __shared__ int sh[1024];
    int idx = blockIdx.x * 1024 + threadIdx.x;
    sh[threadIdx.x] = (idx < NN) ? g_degin[idx] : 0;
    __syncthreads();
    for (int off = 512; off > 0; off >>= 1) {
        if (threadIdx.x < off) sh[threadIdx.x] += sh[threadIdx.x + off];
        __syncthreads();
    }
    if (threadIdx.x == 0) g_partial[blockIdx.x] = sh[0];
}

__global__ void scanB_kernel() {
    __shared__ int sh[128];
    int t = threadIdx.x;
    sh[t] = (t < NB) ? g_partial[t] : 0;
    __syncthreads();
    if (t == 0) {
        int run = 0;
        for (int b = 0; b < NB; b++) { int v = sh[b]; sh[b] = run; run += v; }
        g_rowptr[NN] = run;
    }
    __syncthreads();
    if (t < NB) g_base[t] = sh[t];
}

__global__ void scanC_kernel() {    // warp-shuffle scan
    __shared__ int warpsum[32];
    int tid = threadIdx.x;
    int idx = blockIdx.x * 1024 + tid;
    int lane = tid & 31, w = tid >> 5;
    int v = (idx < NN) ? g_degin[idx] : 0;
    int s = v;
    #pragma unroll
    for (int o = 1; o < 32; o <<= 1) {
        int t = __shfl_up_sync(0xffffffffu, s, o);
        if (lane >= o) s += t;
    }
    if (lane == 31) warpsum[w] = s;
    __syncthreads();
    if (w == 0) {
        int ws = warpsum[lane];
        #pragma unroll
        for (int o = 1; o < 32; o <<= 1) {
            int t = __shfl_up_sync(0xffffffffu, ws, o);
            if (lane >= o) ws += t;
        }
        warpsum[lane] = ws;
    }
    __syncthreads();
    int excl = s - v + (w > 0 ? warpsum[w - 1] : 0) + g_base[blockIdx.x];
    if (idx < NN) {
        g_rowptr[idx] = excl;
        g_cur[idx] = excl;
    }
}

__global__ void scatter_kernel(const int* __restrict__ src, const int* __restrict__ dst) {
    int e = blockIdx.x * blockDim.x + threadIdx.x;
    if (e < NE) {
        int pos = atomicAdd(&g_cur[dst[e]], 1);
        g_csrc[pos] = src[e];
    }
}

// ---- fused gather + FP16 double-GEMM ---------------------------------------
__device__ __forceinline__ unsigned smem_u32(const void* p) {
    return (unsigned)__cvta_generic_to_shared(p);
}
__device__ __forceinline__ void ldsm_x4(unsigned& r0, unsigned& r1, unsigned& r2, unsigned& r3,
                                        unsigned addr) {
    asm volatile("ldmatrix.sync.aligned.m8n8.x4.shared.b16 {%0,%1,%2,%3}, [%4];"
                 : "=r"(r0), "=r"(r1), "=r"(r2), "=r"(r3) : "r"(addr));
}
__device__ __forceinline__ void ldsm_x2t(unsigned& r0, unsigned& r1, unsigned addr) {
    asm volatile("ldmatrix.sync.aligned.m8n8.x2.trans.shared.b16 {%0,%1}, [%2];"
                 : "=r"(r0), "=r"(r1) : "r"(addr));
}
#define MMA_F16(c, a0, a1, a2, a3, b0, b1)                                    \
    asm volatile("mma.sync.aligned.m16n8k16.row.col.f32.f16.f16.f32 "         \
                 "{%0,%1,%2,%3}, {%4,%5,%6,%7}, {%8,%9}, {%0,%1,%2,%3};"      \
                 : "+f"(c[0]), "+f"(c[1]), "+f"(c[2]), "+f"(c[3])             \
                 : "r"(a0), "r"(a1), "r"(a2), "r"(a3), "r"(b0), "r"(b1))

#define AS_STRIDE 136
#define BS_STRIDE 72
#define OFF_AS  0
#define OFF_BS1 (64 * AS_STRIDE)
#define OFF_BS2 (OFF_BS1 + 128 * BS_STRIDE)
#define OFF_HS  (OFF_BS2 + 64 * BS_STRIDE)
#define FUSED_SMEM_HALVES (OFF_HS + 64 * BS_STRIDE)

__global__ void gemm_fused_kernel(const float* __restrict__ rin,
                                  const float* __restrict__ b1,
                                  const float* __restrict__ rout,
                                  __half* __restrict__ Cout,     // h2in [M,64]
                                  int M) {
    extern __shared__ __half sm[];
    __half* As  = sm + OFF_AS;
    __half* Bs1 = sm + OFF_BS1;
    __half* Bs2 = sm + OFF_BS2;
    __half* Hs  = sm + OFF_HS;

    int tid = threadIdx.x;
    int warp = tid >> 5, lane = tid & 31;
    int g = lane >> 2, q = lane & 3;
    int wm = warp & 1, wn = warp >> 1;
    int rowBase = blockIdx.x * 64;
    int l16 = lane & 15, lh = lane >> 4;

    float rs0[2], rs1[2], ro0[2], ro1[2];
    #pragma unroll
    for (int mt = 0; mt < 2; mt++) {
        int r = rowBase + wm * 32 + mt * 16 + g;
        rs0[mt] = (r < M) ? rin[r] : 0.f;
        ro0[mt] = (r < M) ? rout[r] : 0.f;
        rs1[mt] = (r + 8 < M) ? rin[r + 8] : 0.f;
        ro1[mt] = (r + 8 < M) ? rout[r + 8] : 0.f;
    }

    // phase 0: gather — warp w aggregates node rows 8w..8w+7 into As (fp16)
    #pragma unroll 1
    for (int rr = 0; rr < 8; rr++) {
        int row = warp * 8 + rr;
        int node = rowBase + row;
        float4 acc = make_float4(0.f, 0.f, 0.f, 0.f);
        if (node < M) {
            int beg = g_rowptr[node], end = g_rowptr[node + 1];
            int j = beg;
            for (; j + 3 < end; j += 4) {
                int s0 = g_csrc[j],     s1 = g_csrc[j + 1];
                int s2 = g_csrc[j + 2], s3 = g_csrc[j + 3];
                uint2 r0 = ((const uint2*)(g_xs + (size_t)s0 * 128))[lane];
                uint2 r1 = ((const uint2*)(g_xs + (size_t)s1 * 128))[lane];
                uint2 r2 = ((const uint2*)(g_xs + (size_t)s2 * 128))[lane];
                uint2 r3 = ((const uint2*)(g_xs + (size_t)s3 * 128))[lane];
                float2 a0 = __half22float2(*(__half2*)&r0.x), b0 = __half22float2(*(__half2*)&r0.y);
                float2 a1 = __half22float2(*(__half2*)&r1.x), b1v = __half22float2(*(__half2*)&r1.y);
                float2 a2 = __half22float2(*(__half2*)&r2.x), b2 = __half22float2(*(__half2*)&r2.y);
                float2 a3 = __half22float2(*(__half2*)&r3.x), b3 = __half22float2(*(__half2*)&r3.y);
                acc.x += a0.x + a1.x + a2.x + a3.x;
                acc.y += a0.y + a1.y + a2.y + a3.y;
                acc.z += b0.x + b1v.x + b2.x + b3.x;
                acc.w += b0.y + b1v.y + b2.y + b3.y;
            }
            for (; j < end; j++) {
                int s = g_csrc[j];
                uint2 r = ((const uint2*)(g_xs + (size_t)s * 128))[lane];
                float2 a = __half22float2(*(__half2*)&r.x), b = __half22float2(*(__half2*)&r.y);
                acc.x += a.x; acc.y += a.y; acc.z += b.x; acc.w += b.y;
            }
        }
        __half2 h0 = __floats2half2_rn(acc.x, acc.y);
        __half2 h1 = __floats2half2_rn(acc.z, acc.w);
        ((uint2*)(As + row * AS_STRIDE))[lane] = make_uint2(*(unsigned*)&h0, *(unsigned*)&h1);
    }

    float c2[2][2][4] = {};

    for (int qtr = 0; qtr < 4; qtr++) {
        // W1 tile (fp16 direct): [128 k][64 n] -> Bs1
        #pragma unroll
        for (int it = 0; it < 4; it++) {
            int idx = tid + it * 256;        // uint4 index; 8 per k-row
            int krow = idx >> 3;
            int c8 = (idx & 7) * 8;
            *(uint4*)(Bs1 + krow * BS_STRIDE + c8) =
                *(const uint4*)(g_W1h + (size_t)krow * 256 + qtr * 64 + c8);
        }
        __syncthreads();   // As (qtr 0) + Bs1 ready

        // MMA1: c1 = A_tile @ W1_quarter  (64x64, K=128)
        float c1[2][2][4] = {};
        #pragma unroll
        for (int ks = 0; ks < 8; ks++) {
            unsigned a[2][4], b[2][2];
            #pragma unroll
            for (int mt = 0; mt < 2; mt++)
                ldsm_x4(a[mt][0], a[mt][1], a[mt][2], a[mt][3],
                        smem_u32(As + (wm * 32 + mt * 16 + l16) * AS_STRIDE + ks * 16 + lh * 8));
            #pragma unroll
            for (int nt = 0; nt < 2; nt++)
                ldsm_x2t(b[nt][0], b[nt][1],
                         smem_u32(Bs1 + (ks * 16 + l16) * BS_STRIDE + wn * 16 + nt * 8));
            #pragma unroll
            for (int mt = 0; mt < 2; mt++)
                #pragma unroll
                for (int nt = 0; nt < 2; nt++)
                    MMA_F16(c1[mt][nt], a[mt][0], a[mt][1], a[mt][2], a[mt][3],
                            b[nt][0], b[nt][1]);
        }

        // epilogue1: relu(rin*c1 + b1) -> Hs fp16 [64 row][64 col]
        #pragma unroll
        for (int nt = 0; nt < 2; nt++) {
            int cL0 = wn * 16 + nt * 8 + 2 * q;
            float2 bb = *(const float2*)(b1 + qtr * 64 + cL0);
            #pragma unroll
            for (int mt = 0; mt < 2; mt++) {
                int r0 = wm * 32 + mt * 16 + g;
                __half2 h0 = __floats2half2_rn(fmaxf(c1[mt][nt][0] * rs0[mt] + bb.x, 0.f),
                                               fmaxf(c1[mt][nt][1] * rs0[mt] + bb.y, 0.f));
                __half2 h1 = __floats2half2_rn(fmaxf(c1[mt][nt][2] * rs1[mt] + bb.x, 0.f),
                                               fmaxf(c1[mt][nt][3] * rs1[mt] + bb.y, 0.f));
                *(__half2*)(Hs + r0 * BS_STRIDE + cL0) = h0;
                *(__half2*)(Hs + (r0 + 8) * BS_STRIDE + cL0) = h1;
            }
        }

        // W2 tile (fp16 direct): rows qtr*64..+64 -> Bs2
        #pragma unroll
        for (int it = 0; it < 2; it++) {
            int idx = tid + it * 256;
            int krow = idx >> 3;
            int c8 = (idx & 7) * 8;
            *(uint4*)(Bs2 + krow * BS_STRIDE + c8) =
                *(const uint4*)(g_W2h + (size_t)(qtr * 64 + krow) * 64 + c8);
        }
        __syncthreads();   // Hs + Bs2 ready

        // MMA2: c2 += h1_quarter @ W2_quarter  (64x64, K=64)
        #pragma unroll
        for (int ks = 0; ks < 4; ks++) {
            unsigned a[2][4], b[2][2];
            #pragma unroll
            for (int mt = 0; mt < 2; mt++)
                ldsm_x4(a[mt][0], a[mt][1], a[mt][2], a[mt][3],
                        smem_u32(Hs + (wm * 32 + mt * 16 + l16) * BS_STRIDE + ks * 16 + lh * 8));
            #pragma unroll
            for (int nt = 0; nt < 2; nt++)
                ldsm_x2t(b[nt][0], b[nt][1],
                         smem_u32(Bs2 + (ks * 16 + l16) * BS_STRIDE + wn * 16 + nt * 8));
            #pragma unroll
            for (int mt = 0; mt < 2; mt++)
                #pragma unroll
                for (int nt = 0; nt < 2; nt++)
                    MMA_F16(c2[mt][nt], a[mt][0], a[mt][1], a[mt][2], a[mt][3],
                            b[nt][0], b[nt][1]);
        }
        __syncthreads();   // all MMA2 reads done before next quarter's writes
    }

    // final epilogue: h2in = fp16(rout * c2)
    #pragma unroll
    for (int mt = 0; mt < 2; mt++) {
        int r0 = rowBase + wm * 32 + mt * 16 + g;
        #pragma unroll
        for (int nt = 0; nt < 2; nt++) {
            int c0 = wn * 16 + nt * 8 + 2 * q;
            if (r0 < M)
                *(__half2*)(Cout + (size_t)r0 * 64 + c0) =
                    __floats2half2_rn(c2[mt][nt][0] * ro0[mt], c2[mt][nt][1] * ro0[mt]);
            if (r0 + 8 < M)
                *(__half2*)(Cout + (size_t)(r0 + 8) * 64 + c0) =
                    __floats2half2_rn(c2[mt][nt][2] * ro1[mt], c2[mt][nt][3] * ro1[mt]);
        }
    }
}

// ---- layer-2 aggregation fused with mean-pool reduction (fp16 gather) ------
__global__ void agg2_pool_kernel(const int* __restrict__ gid, const float* __restrict__ b2) {
    __shared__ float sv[8][64];
    __shared__ int sg[8];
    int wid = threadIdx.x >> 5, lane = threadIdx.x & 31;
    int node = blockIdx.x * 8 + wid;
    float2 acc = make_float2(0.f, 0.f);
    int gv = -1;
    if (node < NN) {
        int beg = g_rowptr[node], end = g_rowptr[node + 1];
        int j = beg;
        for (; j + 3 < end; j += 4) {
            int s0 = g_csrc[j],     s1 = g_csrc[j + 1];
            int s2 = g_csrc[j + 2], s3 = g_csrc[j + 3];
            float2 v0 = __half22float2(((const __half2*)(g_h2in + (size_t)s0 * 64))[lane]);
            float2 v1 = __half22float2(((const __half2*)(g_h2in + (size_t)s1 * 64))[lane]);
            float2 v2 = __half22float2(((const __half2*)(g_h2in + (size_t)s2 * 64))[lane]);
            float2 v3 = __half22float2(((const __half2*)(g_h2in + (size_t)s3 * 64))[lane]);
            acc.x += v0.x + v1.x + v2.x + v3.x;
            acc.y += v0.y + v1.y + v2.y + v3.y;
        }
        for (; j < end; j++) {
            int s = g_csrc[j];
            float2 v = __half22float2(((const __half2*)(g_h2in + (size_t)s * 64))[lane]);
            acc.x += v.x; acc.y += v.y;
        }
        float ri = g_rin[node];
        float2 bb = ((const float2*)b2)[lane];
        acc.x = fmaxf(acc.x * ri + bb.x, 0.f);
        acc.y = fmaxf(acc.y * ri + bb.y, 0.f);
        gv = gid[node];
    }
    sv[wid][lane * 2]     = acc.x;
    sv[wid][lane * 2 + 1] = acc.y;
    if (lane == 0) sg[wid] = gv;
    __syncthreads();

    if (wid == 0) {
        int c0 = lane * 2;
        float a0 = 0.f, a1 = 0.f;
        int cnt = 0;
        int cur = sg[0];
        #pragma unroll
        for (int w = 0; w < 8; w++) {
            int gw = sg[w];
            if (gw != cur) {
                if (cur >= 0) {
                    atomicAdd(&g_gsum[cur * 64 + c0], a0);
                    atomicAdd(&g_gsum[cur * 64 + c0 + 1], a1);
                    if (lane == 0) atomicAdd(&g_gcnt[cur], cnt);
                }
                a0 = 0.f; a1 = 0.f; cnt = 0; cur = gw;
            }
            if (gw >= 0) { a0 += sv[w][c0]; a1 += sv[w][c0 + 1]; cnt++; }
        }
        if (cur >= 0) {
            atomicAdd(&g_gsum[cur * 64 + c0], a0);
            atomicAdd(&g_gsum[cur * 64 + c0 + 1], a1);
            if (lane == 0) atomicAdd(&g_gcnt[cur], cnt);
        }
    }
}

__global__ void classifier_kernel(const float* __restrict__ Wc1, const float* __restrict__ bc1,
                                  const float* __restrict__ Wc2, const float* __restrict__ bc2,
                                  const float* __restrict__ Wc3, const float* __restrict__ bc3,
                                  const float* __restrict__ Wc4, const float* __restrict__ bc4,
                                  float* __restrict__ out) {
    int g = blockIdx.x * blockDim.x + threadIdx.x;
    if (g >= NG) return;
    float inv = 1.f / fmaxf((float)g_gcnt[g], 1.f);
    float h[64];
    #pragma unroll
    for (int j = 0; j < 64; j++) h[j] = g_gsum[g * 64 + j] * inv;
    float t1[18];
    for (int j = 0; j < 18; j++) {
        float s = bc1[j];
        for (int k = 0; k < 64; k++) s += h[k] * Wc1[k * 18 + j];
        t1[j] = s;
    }
    float t2[12];
    for (int j = 0; j < 12; j++) {
        float s = bc2[j];
        for (int k = 0; k < 18; k++) s += t1[k] * Wc2[k * 12 + j];
        t2[j] = s;
    }
    float t3[6];
    for (int j = 0; j < 6; j++) {
        float s = bc3[j];
        for (int k = 0; k < 12; k++) s += t2[k] * Wc3[k * 6 + j];
        t3[j] = s;
    }
    for (int j = 0; j < 2; j++) {
        float s = bc4[j];
        for (int k = 0; k < 6; k++) s += t3[k] * Wc4[k * 2 + j];
        out[g * 2 + j] = s;
    }
}

// ---------------------------------------------------------------------------
extern "C" void kernel_launch(void* const* d_in, const int* in_sizes, int n_in,
                              void* d_out, int out_size) {
    const float* x   = (const float*)d_in[0];
    const int*   src = (const int*)d_in[1];
    const int*   dst = (const int*)d_in[2];
    const int*   gid = (const int*)d_in[3];
    const float* W1  = (const float*)d_in[4];
    const float* b1  = (const float*)d_in[5];
    const float* W2  = (const float*)d_in[6];
    const float* b2  = (const float*)d_in[7];
    const float* Wc1 = (const float*)d_in[8];
    const float* bc1 = (const float*)d_in[9];
    const float* Wc2 = (const float*)d_in[10];
    const float* bc2 = (const float*)d_in[11];
    const float* Wc3 = (const float*)d_in[12];
    const float* bc3 = (const float*)d_in[13];
    const float* Wc4 = (const float*)d_in[14];
    const float* bc4 = (const float*)d_in[15];
    float* out = (float*)d_out;

    float *p_rin, *p_rout;
    __half* p_h2in;
    cudaGetSymbolAddress((void**)&p_h2in, g_h2in);
    cudaGetSymbolAddress((void**)&p_rin,  g_rin);
    cudaGetSymbolAddress((void**)&p_rout, g_rout);

    static int smem_set = 0;
    const int fused_smem = FUSED_SMEM_HALVES * 2;
    if (!smem_set) {
        cudaFuncSetAttribute(gemm_fused_kernel,
                             cudaFuncAttributeMaxDynamicSharedMemorySize, fused_smem);
        smem_set = 1;
    }

    zero_wpack_kernel<<<256, 256>>>(W1, W2);
    degree_kernel<<<(NE + 255) / 256, 256>>>(src, dst);
    finalize_deg_kernel<<<(NN + 255) / 256, 256>>>();

    // pre-scale + fp16 pack x
    xscale_kernel<<<(NN * 32 + 255) / 256, 256>>>(x);

    // CSR build (dst-major)
    scanA_kernel<<<NB, 1024>>>();
    scanB_kernel<<<1, 128>>>();
    scanC_kernel<<<NB, 1024>>>();
    scatter_kernel<<<(NE + 255) / 256, 256>>>(src, dst);

    // fused gather + fp16 tensor-core double GEMM (fp16 weights direct)
    gemm_fused_kernel<<<(NN + 63) / 64, 256, fused_smem>>>(
        p_rin, b1, p_rout, p_h2in, NN);

    // layer 2 gather + pool (fp16 gather)
    agg2_pool_kernel<<<(NN + 7) / 8, 256>>>(gid, b2);

    classifier_kernel<<<(NG + 255) / 256, 256>>>(Wc1, bc1, Wc2, bc2, Wc3, bc3, Wc4, bc4, out);
}